// round 7
// baseline (speedup 1.0000x reference)
#include <cuda_runtime.h>
#include <cuda_bf16.h>
#include <cstdint>

#define MAX_N   (1 << 17)
#define NMODELS 8
#define H       128
#define TILE    128
#define NCTA    148
#define MLP_THREADS 256

#define BROW 144                 // bytes per int8 image row (128 data + 16 pad)
#define BIMG (H * BROW)          // 18432 bytes per 128x128 int8 image

// ---------------- scratch (device globals; no allocs allowed) ----------------
__device__ int    g_counts[NMODELS];   // zero-init; k_scan re-zeroes each call
__device__ int    g_base[NMODELS + 1]; // [NMODELS] = total points
__device__ int    g_offset[NMODELS];
__device__ int    g_tilebase[NMODELS + 1];
__device__ int    g_total_tiles;
__device__ int    g_idx[MAX_N];
__device__ int    g_perm[MAX_N];
__device__ float4 g_xg[MAX_N];
__device__ __align__(16) char   g_Bq1[16 * BIMG];
__device__ __align__(16) char   g_Bq2[16 * BIMG];
__device__ float  g_sB[16 * H];
__device__ __align__(16) float4 g_W0p[NMODELS * H];

// ---------------- helpers -----------------------------------------------------
__device__ __forceinline__ uint32_t smem_u32(const void* p) {
    uint32_t a;
    asm("{ .reg .u64 t; cvta.to.shared.u64 t, %1; cvt.u32.u64 %0, t; }"
        : "=r"(a) : "l"(p));
    return a;
}
__device__ __forceinline__ void mma_s8(int* d, const uint32_t* a,
                                       uint32_t b0, uint32_t b1) {
    asm volatile(
        "mma.sync.aligned.m16n8k32.row.col.s32.s8.s8.s32 "
        "{%0,%1,%2,%3}, {%4,%5,%6,%7}, {%8,%9}, {%0,%1,%2,%3};"
        : "+r"(d[0]), "+r"(d[1]), "+r"(d[2]), "+r"(d[3])
        : "r"(a[0]), "r"(a[1]), "r"(a[2]), "r"(a[3]), "r"(b0), "r"(b1));
}
__device__ __forceinline__ void ldsm4(uint32_t* r, uint32_t addr) {
    asm volatile("ldmatrix.sync.aligned.m8n8.x4.shared.b16 {%0,%1,%2,%3}, [%4];"
                 : "=r"(r[0]), "=r"(r[1]), "=r"(r[2]), "=r"(r[3]) : "r"(addr));
}
__device__ __forceinline__ uint32_t quant_pair(float v0, float v1, float inv) {
    int Q0 = __float2int_rn(v0 * inv), Q1 = __float2int_rn(v1 * inv);
    int a1 = (Q0 + 64) >> 7, b1 = (Q1 + 64) >> 7;
    int a2 = Q0 - (a1 << 7), b2 = Q1 - (b1 << 7);
    return (uint32_t)(uint8_t)a1 | ((uint32_t)(uint8_t)b1 << 8) |
           ((uint32_t)(uint8_t)a2 << 16) | ((uint32_t)(uint8_t)b2 << 24);
}

// ---------------- model index (bit-exact vs reference) ------------------------
__device__ __forceinline__ int model_index(float x0, float x1, float x2) {
    const float den = 2.0f + 1e-6f;
    int c0 = (int)((x2 + 1.0f) / den * 2.0f);
    int c1 = (int)((x1 + 1.0f) / den * 2.0f);
    int c2 = (int)((x0 + 1.0f) / den * 2.0f);
    return c0 + 2 * c1 + 4 * c2;
}

// ---------------- aux passes --------------------------------------------------
__global__ void k_classify(const float* __restrict__ x, int n) {
    __shared__ int sh[NMODELS];
    if (threadIdx.x < NMODELS) sh[threadIdx.x] = 0;
    __syncthreads();
    int i = blockIdx.x * blockDim.x + threadIdx.x;
    if (i < n) {
        int m = model_index(x[3 * i], x[3 * i + 1], x[3 * i + 2]);
        g_idx[i] = m;
        atomicAdd(&sh[m], 1);
    }
    __syncthreads();
    if (threadIdx.x < NMODELS && sh[threadIdx.x])
        atomicAdd(&g_counts[threadIdx.x], sh[threadIdx.x]);
}

__global__ void k_scan() {
    if (threadIdx.x == 0) {
        int acc = 0, t = 0;
        for (int m = 0; m < NMODELS; m++) {
            int c = g_counts[m];
            g_counts[m] = 0;          // self-reset for next launch/replay
            g_base[m] = acc;
            g_offset[m] = acc;
            g_tilebase[m] = t;
            t += (c + TILE - 1) / TILE;
            acc += c;
        }
        g_base[NMODELS] = acc;
        g_tilebase[NMODELS] = t;
        g_total_tiles = t;
    }
}

__global__ void k_scatter(const float* __restrict__ x,
                          const float* __restrict__ mins,
                          const float* __restrict__ maxs, int n) {
    __shared__ int sh_cnt[NMODELS];
    __shared__ int sh_base[NMODELS];
    int tid = threadIdx.x;
    if (tid < NMODELS) sh_cnt[tid] = 0;
    __syncthreads();
    int i = blockIdx.x * blockDim.x + tid;
    int m = 0, rank = 0;
    if (i < n) {
        m = g_idx[i];
        rank = atomicAdd(&sh_cnt[m], 1);
    }
    __syncthreads();
    if (tid < NMODELS)
        sh_base[tid] = sh_cnt[tid] ? atomicAdd(&g_offset[tid], sh_cnt[tid]) : 0;
    __syncthreads();
    if (i < n) {
        int pos = sh_base[m] + rank;
        g_perm[pos] = i;
        float xn[3];
        #pragma unroll
        for (int d = 0; d < 3; d++) {
            float mn = mins[3 * m + d], mx = maxs[3 * m + d];
            xn[d] = -1.0f + 2.0f * (x[3 * i + d] - mn) / (mx - mn);
        }
        g_xg[pos] = make_float4(xn[0], xn[1], xn[2], 0.0f);
    }
}

// ---------------- weight prep: transpose + int8 fixed-point split -------------
__global__ void k_prep(const float* __restrict__ W1, const float* __restrict__ W2,
                       const float* __restrict__ W0, const float* __restrict__ b0) {
    int t = blockIdx.x * blockDim.x + threadIdx.x;
    if (t < 2048) {
        int lm = t >> 7, n = t & 127;
        const float* W = ((lm >> 3) ? W2 : W1) + (lm & 7) * H * H;
        float mx = 0.f;
        #pragma unroll 8
        for (int k = 0; k < H; k++) mx = fmaxf(mx, fabsf(W[k * H + n]));
        float inv = mx > 0.f ? 16129.0f / mx : 0.f;
        g_sB[lm * H + n] = mx * (1.0f / 16129.0f);
        uint32_t* q1p = (uint32_t*)(g_Bq1 + lm * BIMG + n * BROW);
        uint32_t* q2p = (uint32_t*)(g_Bq2 + lm * BIMG + n * BROW);
        #pragma unroll 4
        for (int k4 = 0; k4 < 32; k4++) {
            uint32_t w1 = 0, w2 = 0;
            #pragma unroll
            for (int b = 0; b < 4; b++) {
                int Q = __float2int_rn(W[(k4 * 4 + b) * H + n] * inv);
                int q1 = (Q + 64) >> 7;
                int q2 = Q - (q1 << 7);
                w1 |= ((uint32_t)(uint8_t)q1) << (8 * b);
                w2 |= ((uint32_t)(uint8_t)q2) << (8 * b);
            }
            q1p[k4] = w1;
            q2p[k4] = w2;
        }
    } else if (t < 3072) {
        int i = t - 2048;
        int m = i >> 7, c = i & 127;
        g_W0p[i] = make_float4(W0[m * 384 + c], W0[m * 384 + 128 + c],
                               W0[m * 384 + 256 + c], b0[m * H + c]);
    }
}

// ---------------- smem layout (bytes) -----------------------------------------
#define SB_IMG(l, img) (((l) * 2 + (img)) * BIMG)
#define SA_Q1  73728
#define SA_Q2  (SA_Q1 + BIMG)
#define SC_W0P 110592
#define SC_SB1 (SC_W0P + 2048)
#define SC_B1  (SC_SB1 + 512)
#define SC_SB2 (SC_B1 + 512)
#define SC_B2  (SC_SB2 + 512)
#define SC_W3  (SC_B2 + 512)
#define SMEM_TOTAL (SC_W3 + 512)   // 115200

__device__ __forceinline__ void quant_rows(const float* v, char* smc,
                                           int r0, int cbase,
                                           float& dA0, float& dA1) {
    float m0 = 0.f, m1 = 0.f;
    #pragma unroll
    for (int nt = 0; nt < 16; nt++) {
        m0 = fmaxf(m0, fmaxf(v[nt * 4 + 0], v[nt * 4 + 1]));
        m1 = fmaxf(m1, fmaxf(v[nt * 4 + 2], v[nt * 4 + 3]));
    }
    m0 = fmaxf(m0, __shfl_xor_sync(~0u, m0, 1));
    m0 = fmaxf(m0, __shfl_xor_sync(~0u, m0, 2));
    m1 = fmaxf(m1, __shfl_xor_sync(~0u, m1, 1));
    m1 = fmaxf(m1, __shfl_xor_sync(~0u, m1, 2));
    float inv0 = m0 > 0.f ? 16129.0f / m0 : 0.f;
    float inv1 = m1 > 0.f ? 16129.0f / m1 : 0.f;
    dA0 = m0 * (1.0f / 16129.0f);
    dA1 = m1 * (1.0f / 16129.0f);
    char* r0q1 = smc + SA_Q1 + r0 * BROW;
    char* r1q1 = r0q1 + 8 * BROW;
    char* r0q2 = smc + SA_Q2 + r0 * BROW;
    char* r1q2 = r0q2 + 8 * BROW;
    #pragma unroll
    for (int nt = 0; nt < 16; nt++) {
        int c = nt * 8 + cbase;
        uint32_t w0 = quant_pair(v[nt * 4 + 0], v[nt * 4 + 1], inv0);
        uint32_t w1 = quant_pair(v[nt * 4 + 2], v[nt * 4 + 3], inv1);
        *(uint16_t*)(r0q1 + c) = (uint16_t)w0;
        *(uint16_t*)(r0q2 + c) = (uint16_t)(w0 >> 16);
        *(uint16_t*)(r1q1 + c) = (uint16_t)w1;
        *(uint16_t*)(r1q2 + c) = (uint16_t)(w1 >> 16);
    }
}

__device__ __forceinline__ void mma_loops(int* hh, int* mid,
                                          uint32_t a1base, uint32_t a2base,
                                          uint32_t bq1base, uint32_t bq2base,
                                          uint32_t b_lane_off) {
    #pragma unroll
    for (int kt = 0; kt < 4; kt++) {
        uint32_t aq1[4], aq2[4];
        ldsm4(aq1, a1base + kt * 32);
        ldsm4(aq2, a2base + kt * 32);
        #pragma unroll
        for (int ntp = 0; ntp < 8; ntp++) {
            uint32_t b1r[4], b2r[4];
            uint32_t off = (uint32_t)(ntp * 16 * BROW + kt * 32) + b_lane_off;
            ldsm4(b1r, bq1base + off);
            ldsm4(b2r, bq2base + off);
            mma_s8(hh + ntp * 8,      aq1, b1r[0], b1r[1]);
            mma_s8(hh + ntp * 8 + 4,  aq1, b1r[2], b1r[3]);
            mma_s8(mid + ntp * 8,     aq1, b2r[0], b2r[1]);
            mma_s8(mid + ntp * 8 + 4, aq1, b2r[2], b2r[3]);
            mma_s8(mid + ntp * 8,     aq2, b1r[0], b1r[1]);
            mma_s8(mid + ntp * 8 + 4, aq2, b1r[2], b1r[3]);
        }
    }
}

// ---------------- persistent int8 fused-MLP kernel ----------------------------
__global__ void __launch_bounds__(MLP_THREADS, 1)
k_mlp(const float* __restrict__ W3, const float* __restrict__ b1g,
      const float* __restrict__ b2g, const float* __restrict__ b3g,
      float* __restrict__ out) {
    extern __shared__ char smc[];
    const uint32_t sbase = smem_u32(smc);
    const int tid  = threadIdx.x;
    const int wid  = tid >> 5;
    const int lane = tid & 31;
    const int grp  = lane >> 2;
    const int cbase = 2 * (lane & 3);
    const int r0l  = wid * 16 + grp;
    const int r1l  = r0l + 8;

    const uint32_t b_lane_off =
        (uint32_t)(((lane & 7) + ((lane & 16) ? 8 : 0)) * BROW + ((lane & 8) ? 16 : 0));
    const uint32_t a_lane_off =
        (uint32_t)(((lane & 7) + ((lane & 8) ? 8 : 0)) * BROW + ((lane & 16) ? 16 : 0));
    const uint32_t a1base = sbase + SA_Q1 + (uint32_t)(wid * 16 * BROW) + a_lane_off;
    const uint32_t a2base = sbase + SA_Q2 + (uint32_t)(wid * 16 * BROW) + a_lane_off;

    float4* W0ps = (float4*)(smc + SC_W0P);
    float*  sB1s = (float*)(smc + SC_SB1);
    float*  b1s  = (float*)(smc + SC_B1);
    float*  sB2s = (float*)(smc + SC_SB2);
    float*  b2s  = (float*)(smc + SC_B2);
    float*  w3s  = (float*)(smc + SC_W3);

    const int T = g_total_tiles;
    const int start = (int)((long long)blockIdx.x * T / NCTA);
    const int end   = (int)((long long)(blockIdx.x + 1) * T / NCTA);

    int cur_m = -1;
    float b3v = 0.0f;

    for (int t = start; t < end; t++) {
        int m = 0;
        while (m < NMODELS - 1 && t >= g_tilebase[m + 1]) m++;

        if (m != cur_m) {
            __syncthreads();
            const uint4* s10 = (const uint4*)(g_Bq1 + (0 * 8 + m) * BIMG);
            const uint4* s11 = (const uint4*)(g_Bq2 + (0 * 8 + m) * BIMG);
            const uint4* s20 = (const uint4*)(g_Bq1 + (1 * 8 + m) * BIMG);
            const uint4* s21 = (const uint4*)(g_Bq2 + (1 * 8 + m) * BIMG);
            uint4* d10 = (uint4*)(smc + SB_IMG(0, 0));
            uint4* d11 = (uint4*)(smc + SB_IMG(0, 1));
            uint4* d20 = (uint4*)(smc + SB_IMG(1, 0));
            uint4* d21 = (uint4*)(smc + SB_IMG(1, 1));
            for (int i = tid; i < BIMG / 16; i += MLP_THREADS) {
                d10[i] = s10[i];
                d11[i] = s11[i];
                d20[i] = s20[i];
                d21[i] = s21[i];
            }
            if (tid < H) {
                W0ps[tid] = g_W0p[m * H + tid];
                sB1s[tid] = g_sB[(0 * 8 + m) * H + tid];
                sB2s[tid] = g_sB[(1 * 8 + m) * H + tid];
                b1s[tid]  = b1g[m * H + tid];
                b2s[tid]  = b2g[m * H + tid];
                w3s[tid]  = W3[m * H + tid];
            }
            b3v = b3g[m];
            cur_m = m;
            __syncthreads();
        }

        const int row0 = g_base[m] + (t - g_tilebase[m]) * TILE;
        const int rows = min(TILE, g_base[m + 1] - row0);

        // ---- layer 0 ---------------------------------------------------------
        float4 xa = (r0l < rows) ? g_xg[row0 + r0l] : make_float4(0.f, 0.f, 0.f, 0.f);
        float4 xb = (r1l < rows) ? g_xg[row0 + r1l] : make_float4(0.f, 0.f, 0.f, 0.f);

        float v[64];
        #pragma unroll
        for (int nt = 0; nt < 16; nt++) {
            int c = nt * 8 + cbase;
            float4 wA = W0ps[c], wB = W0ps[c + 1];
            v[nt * 4 + 0] = fmaxf(fmaf(xa.x, wA.x, fmaf(xa.y, wA.y, fmaf(xa.z, wA.z, wA.w))), 0.f);
            v[nt * 4 + 1] = fmaxf(fmaf(xa.x, wB.x, fmaf(xa.y, wB.y, fmaf(xa.z, wB.z, wB.w))), 0.f);
            v[nt * 4 + 2] = fmaxf(fmaf(xb.x, wA.x, fmaf(xb.y, wA.y, fmaf(xb.z, wA.z, wA.w))), 0.f);
            v[nt * 4 + 3] = fmaxf(fmaf(xb.x, wB.x, fmaf(xb.y, wB.y, fmaf(xb.z, wB.z, wB.w))), 0.f);
        }
        float dA0, dA1;
        quant_rows(v, smc, r0l, cbase, dA0, dA1);
        __syncwarp();

        // ---- layer 1 ---------------------------------------------------------
        int hh[64], mid[64];
        #pragma unroll
        for (int i = 0; i < 64; i++) { hh[i] = 0; mid[i] = 0; }
        mma_loops(hh, mid, a1base, a2base,
                  sbase + SB_IMG(0, 0), sbase + SB_IMG(0, 1), b_lane_off);
        __syncwarp();

        #pragma unroll
        for (int nt = 0; nt < 16; nt++) {
            int c = nt * 8 + cbase;
            float2 sp = *(const float2*)(sB1s + c);
            float2 bp = *(const float2*)(b1s + c);
            int i0 = nt * 4;
            float c0 = fmaf(16384.f, (float)hh[i0 + 0], 128.f * (float)mid[i0 + 0]);
            float c1 = fmaf(16384.f, (float)hh[i0 + 1], 128.f * (float)mid[i0 + 1]);
            float c2 = fmaf(16384.f, (float)hh[i0 + 2], 128.f * (float)mid[i0 + 2]);
            float c3 = fmaf(16384.f, (float)hh[i0 + 3], 128.f * (float)mid[i0 + 3]);
            v[i0 + 0] = fmaxf(fmaf(c0, dA0 * sp.x, bp.x), 0.f);
            v[i0 + 1] = fmaxf(fmaf(c1, dA0 * sp.y, bp.y), 0.f);
            v[i0 + 2] = fmaxf(fmaf(c2, dA1 * sp.x, bp.x), 0.f);
            v[i0 + 3] = fmaxf(fmaf(c3, dA1 * sp.y, bp.y), 0.f);
        }
        float dB0, dB1;
        quant_rows(v, smc, r0l, cbase, dB0, dB1);
        __syncwarp();

        // ---- layer 2 ---------------------------------------------------------
        #pragma unroll
        for (int i = 0; i < 64; i++) { hh[i] = 0; mid[i] = 0; }
        mma_loops(hh, mid, a1base, a2base,
                  sbase + SB_IMG(1, 0), sbase + SB_IMG(1, 1), b_lane_off);

        // ---- layer 3 ---------------------------------------------------------
        float s0 = 0.f, s1 = 0.f;
        #pragma unroll
        for (int nt = 0; nt < 16; nt++) {
            int c = nt * 8 + cbase;
            float2 sp = *(const float2*)(sB2s + c);
            float2 bp = *(const float2*)(b2s + c);
            float2 wp = *(const float2*)(w3s + c);
            int i0 = nt * 4;
            float c0 = fmaf(16384.f, (float)hh[i0 + 0], 128.f * (float)mid[i0 + 0]);
            float c1 = fmaf(16384.f, (float)hh[i0 + 1], 128.f * (float)mid[i0 + 1]);
            float c2 = fmaf(16384.f, (float)hh[i0 + 2], 128.f * (float)mid[i0 + 2]);
            float c3 = fmaf(16384.f, (float)hh[i0 + 3], 128.f * (float)mid[i0 + 3]);
            s0 = fmaf(fmaxf(fmaf(c0, dB0 * sp.x, bp.x), 0.f), wp.x, s0);
            s0 = fmaf(fmaxf(fmaf(c1, dB0 * sp.y, bp.y), 0.f), wp.y, s0);
            s1 = fmaf(fmaxf(fmaf(c2, dB1 * sp.x, bp.x), 0.f), wp.x, s1);
            s1 = fmaf(fmaxf(fmaf(c3, dB1 * sp.y, bp.y), 0.f), wp.y, s1);
        }
        s0 += __shfl_xor_sync(0xffffffffu, s0, 1);
        s0 += __shfl_xor_sync(0xffffffffu, s0, 2);
        s1 += __shfl_xor_sync(0xffffffffu, s1, 1);
        s1 += __shfl_xor_sync(0xffffffffu, s1, 2);
        if ((lane & 3) == 0) {
            if (r0l < rows) out[g_perm[row0 + r0l]] = s0 + b3v;
            if (r1l < rows) out[g_perm[row0 + r1l]] = s1 + b3v;
        }
        __syncwarp();
    }
}

// ---------------- launch -------------------------------------------------------
extern "C" void kernel_launch(void* const* d_in, const int* in_sizes, int n_in,
                              void* d_out, int out_size) {
    const float* x    = (const float*)d_in[0];
    const float* W0   = (const float*)d_in[1];
    const float* b0   = (const float*)d_in[2];
    const float* W1   = (const float*)d_in[3];
    const float* b1   = (const float*)d_in[4];
    const float* W2   = (const float*)d_in[5];
    const float* b2   = (const float*)d_in[6];
    const float* W3   = (const float*)d_in[7];
    const float* b3   = (const float*)d_in[8];
    const float* mins = (const float*)d_in[9];
    const float* maxs = (const float*)d_in[10];
    float* out = (float*)d_out;

    const int n = in_sizes[0] / 3;

    cudaFuncSetAttribute(k_mlp, cudaFuncAttributeMaxDynamicSharedMemorySize,
                         SMEM_TOTAL);

    int blocks = (n + 255) / 256;
    k_classify<<<blocks, 256>>>(x, n);
    k_scan<<<1, 32>>>();
    k_scatter<<<blocks, 256>>>(x, mins, maxs, n);
    k_prep<<<(3072 + 255) / 256, 256>>>(W1, W2, W0, b0);

    k_mlp<<<NCTA, MLP_THREADS, SMEM_TOTAL>>>(W3, b1, b2, b3, out);
}

// round 10
// speedup vs baseline: 1.0294x; 1.0294x over previous
#include <cuda_runtime.h>
#include <cuda_bf16.h>
#include <cstdint>

#define MAX_N   (1 << 17)
#define NMODELS 8
#define H       128
#define TILE    128
#define NCTA    148
#define MLP_THREADS 256

#define BROW 144                 // bytes per int8 image row (128 data + 16 pad)
#define BIMG (H * BROW)          // 18432 bytes per 128x128 int8 image

// ---------------- scratch (device globals; no allocs allowed) ----------------
__device__ int    g_counts[NMODELS];   // zero-init; k_scan re-zeroes each call
__device__ int    g_base[NMODELS + 1];
__device__ int    g_offset[NMODELS];
__device__ int    g_tilebase[NMODELS + 1];
__device__ int    g_total_tiles;
__device__ int    g_idx[MAX_N];
__device__ int    g_perm[MAX_N];
__device__ float4 g_xg[MAX_N];
__device__ __align__(16) char   g_Bq1[16 * BIMG];
__device__ __align__(16) char   g_Bq2[16 * BIMG];
__device__ float  g_sB[16 * H];
__device__ __align__(16) float4 g_W0p[NMODELS * H];

// ---------------- helpers -----------------------------------------------------
__device__ __forceinline__ uint32_t smem_u32(const void* p) {
    uint32_t a;
    asm("{ .reg .u64 t; cvta.to.shared.u64 t, %1; cvt.u32.u64 %0, t; }"
        : "=r"(a) : "l"(p));
    return a;
}
__device__ __forceinline__ void mma_s8(int* d, const uint32_t* a,
                                       uint32_t b0, uint32_t b1) {
    asm volatile(
        "mma.sync.aligned.m16n8k32.row.col.s32.s8.s8.s32 "
        "{%0,%1,%2,%3}, {%4,%5,%6,%7}, {%8,%9}, {%0,%1,%2,%3};"
        : "+r"(d[0]), "+r"(d[1]), "+r"(d[2]), "+r"(d[3])
        : "r"(a[0]), "r"(a[1]), "r"(a[2]), "r"(a[3]), "r"(b0), "r"(b1));
}
__device__ __forceinline__ void ldsm4(uint32_t* r, uint32_t addr) {
    asm volatile("ldmatrix.sync.aligned.m8n8.x4.shared.b16 {%0,%1,%2,%3}, [%4];"
                 : "=r"(r[0]), "=r"(r[1]), "=r"(r[2]), "=r"(r[3]) : "r"(addr));
}
__device__ __forceinline__ uint32_t quant_pair(float v0, float v1, float inv) {
    int Q0 = __float2int_rn(v0 * inv), Q1 = __float2int_rn(v1 * inv);
    int a1 = (Q0 + 64) >> 7, b1 = (Q1 + 64) >> 7;
    int a2 = Q0 - (a1 << 7), b2 = Q1 - (b1 << 7);
    return (uint32_t)(uint8_t)a1 | ((uint32_t)(uint8_t)b1 << 8) |
           ((uint32_t)(uint8_t)a2 << 16) | ((uint32_t)(uint8_t)b2 << 24);
}

// ---------------- model index (bit-exact vs reference) ------------------------
__device__ __forceinline__ int model_index(float x0, float x1, float x2) {
    const float den = 2.0f + 1e-6f;
    int c0 = (int)((x2 + 1.0f) / den * 2.0f);
    int c1 = (int)((x1 + 1.0f) / den * 2.0f);
    int c2 = (int)((x0 + 1.0f) / den * 2.0f);
    return c0 + 2 * c1 + 4 * c2;
}

// ---------------- aux passes --------------------------------------------------
__global__ void k_classify(const float* __restrict__ x, int n) {
    __shared__ int sh[NMODELS];
    if (threadIdx.x < NMODELS) sh[threadIdx.x] = 0;
    __syncthreads();
    int i = blockIdx.x * blockDim.x + threadIdx.x;
    if (i < n) {
        int m = model_index(x[3 * i], x[3 * i + 1], x[3 * i + 2]);
        g_idx[i] = m;
        atomicAdd(&sh[m], 1);
    }
    __syncthreads();
    if (threadIdx.x < NMODELS && sh[threadIdx.x])
        atomicAdd(&g_counts[threadIdx.x], sh[threadIdx.x]);
}

__global__ void k_scan() {
    if (threadIdx.x == 0) {
        int acc = 0, t = 0;
        for (int m = 0; m < NMODELS; m++) {
            int c = g_counts[m];
            g_counts[m] = 0;          // self-reset for next launch/replay
            g_base[m] = acc;
            g_offset[m] = acc;
            g_tilebase[m] = t;
            t += (c + TILE - 1) / TILE;
            acc += c;
        }
        g_base[NMODELS] = acc;
        g_tilebase[NMODELS] = t;
        g_total_tiles = t;
    }
}

// scatter (blocks [0, SB)) + weight prep (blocks [SB, SB+16)) + W0 pack (block SB+16)
__global__ void k_scatter_prep(const float* __restrict__ x,
                               const float* __restrict__ mins,
                               const float* __restrict__ maxs, int n, int SB,
                               const float* __restrict__ W0,
                               const float* __restrict__ b0,
                               const float* __restrict__ W1,
                               const float* __restrict__ W2) {
    const int blk = blockIdx.x;
    const int tid = threadIdx.x;
    if (blk < SB) {
        __shared__ int sh_cnt[NMODELS];
        __shared__ int sh_base[NMODELS];
        if (tid < NMODELS) sh_cnt[tid] = 0;
        __syncthreads();
        int i = blk * blockDim.x + tid;
        int m = 0, rank = 0;
        if (i < n) {
            m = g_idx[i];
            rank = atomicAdd(&sh_cnt[m], 1);
        }
        __syncthreads();
        if (tid < NMODELS)
            sh_base[tid] = sh_cnt[tid] ? atomicAdd(&g_offset[tid], sh_cnt[tid]) : 0;
        __syncthreads();
        if (i < n) {
            int pos = sh_base[m] + rank;
            g_perm[pos] = i;
            float xn[3];
            #pragma unroll
            for (int d = 0; d < 3; d++) {
                float mn = mins[3 * m + d], mx = maxs[3 * m + d];
                xn[d] = -1.0f + 2.0f * (x[3 * i + d] - mn) / (mx - mn);
            }
            g_xg[pos] = make_float4(xn[0], xn[1], xn[2], 0.0f);
        }
    } else if (blk < SB + 16) {
        // weight quantization: 2 threads per (lm, n) output neuron
        int t = (blk - SB) * 256 + tid;        // 0..4095
        int pair = t >> 1;                     // lm*128 + n
        int half = t & 1;
        int lm = pair >> 7, nn = pair & 127;
        const float* W = ((lm >> 3) ? W2 : W1) + (lm & 7) * H * H;
        int k0 = half * 64;
        float mx = 0.f;
        #pragma unroll 8
        for (int k = 0; k < 64; k++) mx = fmaxf(mx, fabsf(W[(k0 + k) * H + nn]));
        mx = fmaxf(mx, __shfl_xor_sync(0xffffffffu, mx, 1));
        float inv = mx > 0.f ? 16129.0f / mx : 0.f;
        if (half == 0) g_sB[lm * H + nn] = mx * (1.0f / 16129.0f);
        uint32_t* q1p = (uint32_t*)(g_Bq1 + lm * BIMG + nn * BROW) + half * 16;
        uint32_t* q2p = (uint32_t*)(g_Bq2 + lm * BIMG + nn * BROW) + half * 16;
        #pragma unroll 4
        for (int k4 = 0; k4 < 16; k4++) {
            uint32_t w1 = 0, w2 = 0;
            #pragma unroll
            for (int b = 0; b < 4; b++) {
                int Q = __float2int_rn(W[(k0 + k4 * 4 + b) * H + nn] * inv);
                int q1 = (Q + 64) >> 7;
                int q2 = Q - (q1 << 7);
                w1 |= ((uint32_t)(uint8_t)q1) << (8 * b);
                w2 |= ((uint32_t)(uint8_t)q2) << (8 * b);
            }
            q1p[k4] = w1;
            q2p[k4] = w2;
        }
    } else {
        for (int i = tid; i < NMODELS * H; i += 256) {
            int m = i >> 7, c = i & 127;
            g_W0p[i] = make_float4(W0[m * 384 + c], W0[m * 384 + 128 + c],
                                   W0[m * 384 + 256 + c], b0[m * H + c]);
        }
    }
}

// ---------------- smem layout (bytes) -----------------------------------------
#define SB_IMG(l, img) (((l) * 2 + (img)) * BIMG)
#define SA_Q1  73728
#define SA_Q2  (SA_Q1 + BIMG)
#define SC_W0P 110592
#define SC_SB1 (SC_W0P + 2048)
#define SC_B1  (SC_SB1 + 512)
#define SC_SB2 (SC_B1 + 512)
#define SC_B2  (SC_SB2 + 512)
#define SC_W3  (SC_B2 + 512)
#define SMEM_TOTAL (SC_W3 + 512)   // 115200

// quantize this thread's 64 v-values into the A images (maxes precomputed)
__device__ __forceinline__ void quant_store(const float* v, char* smc,
                                            int r0, int cbase,
                                            float m0, float m1,
                                            float& d0, float& d1) {
    m0 = fmaxf(m0, __shfl_xor_sync(0xffffffffu, m0, 1));
    m0 = fmaxf(m0, __shfl_xor_sync(0xffffffffu, m0, 2));
    m1 = fmaxf(m1, __shfl_xor_sync(0xffffffffu, m1, 1));
    m1 = fmaxf(m1, __shfl_xor_sync(0xffffffffu, m1, 2));
    float inv0 = m0 > 0.f ? 16129.0f / m0 : 0.f;
    float inv1 = m1 > 0.f ? 16129.0f / m1 : 0.f;
    d0 = m0 * (1.0f / 16129.0f);
    d1 = m1 * (1.0f / 16129.0f);
    char* r0q1 = smc + SA_Q1 + r0 * BROW;
    char* r1q1 = r0q1 + 8 * BROW;
    char* r0q2 = smc + SA_Q2 + r0 * BROW;
    char* r1q2 = r0q2 + 8 * BROW;
    #pragma unroll
    for (int nt = 0; nt < 16; nt++) {
        int c = nt * 8 + cbase;
        uint32_t w0 = quant_pair(v[nt * 4 + 0], v[nt * 4 + 1], inv0);
        uint32_t w1 = quant_pair(v[nt * 4 + 2], v[nt * 4 + 3], inv1);
        *(uint16_t*)(r0q1 + c) = (uint16_t)w0;
        *(uint16_t*)(r0q2 + c) = (uint16_t)(w0 >> 16);
        *(uint16_t*)(r1q1 + c) = (uint16_t)w1;
        *(uint16_t*)(r1q2 + c) = (uint16_t)(w1 >> 16);
    }
}

__device__ __forceinline__ void load_afrags(uint32_t* aq1, uint32_t* aq2,
                                            uint32_t a1base, uint32_t a2base) {
    #pragma unroll
    for (int kt = 0; kt < 4; kt++) {
        ldsm4(aq1 + kt * 4, a1base + kt * 32);
        ldsm4(aq2 + kt * 4, a2base + kt * 32);
    }
}

// one output-column-pair (n=16) worth of MMAs; only 16 int accumulators live
__device__ __forceinline__ void mma_ntp(int* hh, int* mid,
                                        const uint32_t* aq1, const uint32_t* aq2,
                                        uint32_t bq1base, uint32_t bq2base,
                                        int ntp, uint32_t b_lane_off) {
    #pragma unroll
    for (int kt = 0; kt < 4; kt++) {
        uint32_t b1r[4], b2r[4];
        uint32_t off = (uint32_t)(ntp * 16 * BROW + kt * 32) + b_lane_off;
        ldsm4(b1r, bq1base + off);
        ldsm4(b2r, bq2base + off);
        mma_s8(hh,      aq1 + kt * 4, b1r[0], b1r[1]);
        mma_s8(hh + 4,  aq1 + kt * 4, b1r[2], b1r[3]);
        mma_s8(mid,     aq1 + kt * 4, b2r[0], b2r[1]);
        mma_s8(mid + 4, aq1 + kt * 4, b2r[2], b2r[3]);
        mma_s8(mid,     aq2 + kt * 4, b1r[0], b1r[1]);
        mma_s8(mid + 4, aq2 + kt * 4, b1r[2], b1r[3]);
    }
}

// ---------------- persistent int8 fused-MLP kernel ----------------------------
__global__ void __launch_bounds__(MLP_THREADS, 1)
k_mlp(const float* __restrict__ W3, const float* __restrict__ b1g,
      const float* __restrict__ b2g, const float* __restrict__ b3g,
      float* __restrict__ out) {
    extern __shared__ char smc[];
    const uint32_t sbase = smem_u32(smc);
    const int tid  = threadIdx.x;
    const int wid  = tid >> 5;
    const int lane = tid & 31;
    const int grp  = lane >> 2;
    const int cbase = 2 * (lane & 3);
    const int r0l  = wid * 16 + grp;
    const int r1l  = r0l + 8;

    const uint32_t b_lane_off =
        (uint32_t)(((lane & 7) + ((lane & 16) ? 8 : 0)) * BROW + ((lane & 8) ? 16 : 0));
    const uint32_t a_lane_off =
        (uint32_t)(((lane & 7) + ((lane & 8) ? 8 : 0)) * BROW + ((lane & 16) ? 16 : 0));
    const uint32_t a1base = sbase + SA_Q1 + (uint32_t)(wid * 16 * BROW) + a_lane_off;
    const uint32_t a2base = sbase + SA_Q2 + (uint32_t)(wid * 16 * BROW) + a_lane_off;

    float4* W0ps = (float4*)(smc + SC_W0P);
    float*  sB1s = (float*)(smc + SC_SB1);
    float*  b1s  = (float*)(smc + SC_B1);
    float*  sB2s = (float*)(smc + SC_SB2);
    float*  b2s  = (float*)(smc + SC_B2);
    float*  w3s  = (float*)(smc + SC_W3);

    const int T = g_total_tiles;
    const int start = (int)((long long)blockIdx.x * T / NCTA);
    const int end   = (int)((long long)(blockIdx.x + 1) * T / NCTA);

    int cur_m = -1;
    float b3v = 0.0f;

    for (int t = start; t < end; t++) {
        int m = 0;
        while (m < NMODELS - 1 && t >= g_tilebase[m + 1]) m++;

        if (m != cur_m) {
            __syncthreads();
            const uint4* s10 = (const uint4*)(g_Bq1 + (0 * 8 + m) * BIMG);
            const uint4* s11 = (const uint4*)(g_Bq2 + (0 * 8 + m) * BIMG);
            const uint4* s20 = (const uint4*)(g_Bq1 + (1 * 8 + m) * BIMG);
            const uint4* s21 = (const uint4*)(g_Bq2 + (1 * 8 + m) * BIMG);
            uint4* d10 = (uint4*)(smc + SB_IMG(0, 0));
            uint4* d11 = (uint4*)(smc + SB_IMG(0, 1));
            uint4* d20 = (uint4*)(smc + SB_IMG(1, 0));
            uint4* d21 = (uint4*)(smc + SB_IMG(1, 1));
            for (int i = tid; i < BIMG / 16; i += MLP_THREADS) {
                d10[i] = s10[i];
                d11[i] = s11[i];
                d20[i] = s20[i];
                d21[i] = s21[i];
            }
            if (tid < H) {
                W0ps[tid] = g_W0p[m * H + tid];
                sB1s[tid] = g_sB[(0 * 8 + m) * H + tid];
                sB2s[tid] = g_sB[(1 * 8 + m) * H + tid];
                b1s[tid]  = b1g[m * H + tid];
                b2s[tid]  = b2g[m * H + tid];
                w3s[tid]  = W3[m * H + tid];
            }
            b3v = b3g[m];
            cur_m = m;
            __syncthreads();
        }

        const int row0 = g_base[m] + (t - g_tilebase[m]) * TILE;
        const int rows = min(TILE, g_base[m + 1] - row0);

        // ---- layer 0 ---------------------------------------------------------
        float4 xa = (r0l < rows) ? g_xg[row0 + r0l] : make_float4(0.f, 0.f, 0.f, 0.f);
        float4 xb = (r1l < rows) ? g_xg[row0 + r1l] : make_float4(0.f, 0.f, 0.f, 0.f);

        float v[64];
        float m0 = 0.f, m1 = 0.f;
        #pragma unroll
        for (int nt = 0; nt < 16; nt++) {
            int c = nt * 8 + cbase;
            float4 wA = W0ps[c], wB = W0ps[c + 1];
            float u0 = fmaxf(fmaf(xa.x, wA.x, fmaf(xa.y, wA.y, fmaf(xa.z, wA.z, wA.w))), 0.f);
            float u1 = fmaxf(fmaf(xa.x, wB.x, fmaf(xa.y, wB.y, fmaf(xa.z, wB.z, wB.w))), 0.f);
            float u2 = fmaxf(fmaf(xb.x, wA.x, fmaf(xb.y, wA.y, fmaf(xb.z, wA.z, wA.w))), 0.f);
            float u3 = fmaxf(fmaf(xb.x, wB.x, fmaf(xb.y, wB.y, fmaf(xb.z, wB.z, wB.w))), 0.f);
            v[nt * 4 + 0] = u0; v[nt * 4 + 1] = u1;
            v[nt * 4 + 2] = u2; v[nt * 4 + 3] = u3;
            m0 = fmaxf(m0, fmaxf(u0, u1));
            m1 = fmaxf(m1, fmaxf(u2, u3));
        }
        float dA0, dA1;
        quant_store(v, smc, r0l, cbase, m0, m1, dA0, dA1);
        __syncwarp();

        // ---- layer 1: per-column-pair MMA + fused epilogue -------------------
        {
            uint32_t aq1[16], aq2[16];
            load_afrags(aq1, aq2, a1base, a2base);
            m0 = 0.f; m1 = 0.f;
            #pragma unroll
            for (int ntp = 0; ntp < 8; ntp++) {
                int hh[8], mid[8];
                #pragma unroll
                for (int i = 0; i < 8; i++) { hh[i] = 0; mid[i] = 0; }
                mma_ntp(hh, mid, aq1, aq2,
                        sbase + SB_IMG(0, 0), sbase + SB_IMG(0, 1), ntp, b_lane_off);
                #pragma unroll
                for (int h2 = 0; h2 < 2; h2++) {
                    int nt = 2 * ntp + h2;
                    int c = nt * 8 + cbase;
                    float2 sp = *(const float2*)(sB1s + c);
                    float2 bp = *(const float2*)(b1s + c);
                    const int* ac = hh + h2 * 4;
                    const int* mm = mid + h2 * 4;
                    float c0 = fmaf(16384.f, (float)ac[0], 128.f * (float)mm[0]);
                    float c1 = fmaf(16384.f, (float)ac[1], 128.f * (float)mm[1]);
                    float c2 = fmaf(16384.f, (float)ac[2], 128.f * (float)mm[2]);
                    float c3 = fmaf(16384.f, (float)ac[3], 128.f * (float)mm[3]);
                    float u0 = fmaxf(fmaf(c0, dA0 * sp.x, bp.x), 0.f);
                    float u1 = fmaxf(fmaf(c1, dA0 * sp.y, bp.y), 0.f);
                    float u2 = fmaxf(fmaf(c2, dA1 * sp.x, bp.x), 0.f);
                    float u3 = fmaxf(fmaf(c3, dA1 * sp.y, bp.y), 0.f);
                    v[nt * 4 + 0] = u0; v[nt * 4 + 1] = u1;
                    v[nt * 4 + 2] = u2; v[nt * 4 + 3] = u3;
                    m0 = fmaxf(m0, fmaxf(u0, u1));
                    m1 = fmaxf(m1, fmaxf(u2, u3));
                }
            }
        }
        __syncwarp();       // all lanes done reading A images for layer 1
        float dB0, dB1;
        quant_store(v, smc, r0l, cbase, m0, m1, dB0, dB1);
        __syncwarp();

        // ---- layer 2 + layer 3 (epilogue reduces straight into s0/s1) --------
        float s0 = 0.f, s1 = 0.f;
        {
            uint32_t aq1[16], aq2[16];
            load_afrags(aq1, aq2, a1base, a2base);
            #pragma unroll
            for (int ntp = 0; ntp < 8; ntp++) {
                int hh[8], mid[8];
                #pragma unroll
                for (int i = 0; i < 8; i++) { hh[i] = 0; mid[i] = 0; }
                mma_ntp(hh, mid, aq1, aq2,
                        sbase + SB_IMG(1, 0), sbase + SB_IMG(1, 1), ntp, b_lane_off);
                #pragma unroll
                for (int h2 = 0; h2 < 2; h2++) {
                    int nt = 2 * ntp + h2;
                    int c = nt * 8 + cbase;
                    float2 sp = *(const float2*)(sB2s + c);
                    float2 bp = *(const float2*)(b2s + c);
                    float2 wp = *(const float2*)(w3s + c);
                    const int* ac = hh + h2 * 4;
                    const int* mm = mid + h2 * 4;
                    float c0 = fmaf(16384.f, (float)ac[0], 128.f * (float)mm[0]);
                    float c1 = fmaf(16384.f, (float)ac[1], 128.f * (float)mm[1]);
                    float c2 = fmaf(16384.f, (float)ac[2], 128.f * (float)mm[2]);
                    float c3 = fmaf(16384.f, (float)ac[3], 128.f * (float)mm[3]);
                    s0 = fmaf(fmaxf(fmaf(c0, dB0 * sp.x, bp.x), 0.f), wp.x, s0);
                    s0 = fmaf(fmaxf(fmaf(c1, dB0 * sp.y, bp.y), 0.f), wp.y, s0);
                    s1 = fmaf(fmaxf(fmaf(c2, dB1 * sp.x, bp.x), 0.f), wp.x, s1);
                    s1 = fmaf(fmaxf(fmaf(c3, dB1 * sp.y, bp.y), 0.f), wp.y, s1);
                }
            }
        }
        s0 += __shfl_xor_sync(0xffffffffu, s0, 1);
        s0 += __shfl_xor_sync(0xffffffffu, s0, 2);
        s1 += __shfl_xor_sync(0xffffffffu, s1, 1);
        s1 += __shfl_xor_sync(0xffffffffu, s1, 2);
        if ((lane & 3) == 0) {
            if (r0l < rows) out[g_perm[row0 + r0l]] = s0 + b3v;
            if (r1l < rows) out[g_perm[row0 + r1l]] = s1 + b3v;
        }
        __syncwarp();
    }
}

// ---------------- launch -------------------------------------------------------
extern "C" void kernel_launch(void* const* d_in, const int* in_sizes, int n_in,
                              void* d_out, int out_size) {
    const float* x    = (const float*)d_in[0];
    const float* W0   = (const float*)d_in[1];
    const float* b0   = (const float*)d_in[2];
    const float* W1   = (const float*)d_in[3];
    const float* b1   = (const float*)d_in[4];
    const float* W2   = (const float*)d_in[5];
    const float* b2   = (const float*)d_in[6];
    const float* W3   = (const float*)d_in[7];
    const float* b3   = (const float*)d_in[8];
    const float* mins = (const float*)d_in[9];
    const float* maxs = (const float*)d_in[10];
    float* out = (float*)d_out;

    const int n = in_sizes[0] / 3;

    cudaFuncSetAttribute(k_mlp, cudaFuncAttributeMaxDynamicSharedMemorySize,
                         SMEM_TOTAL);

    int blocks = (n + 255) / 256;
    k_classify<<<blocks, 256>>>(x, n);
    k_scan<<<1, 32>>>();
    k_scatter_prep<<<blocks + 17, 256>>>(x, mins, maxs, n, blocks,
                                         W0, b0, W1, W2);

    k_mlp<<<NCTA, MLP_THREADS, SMEM_TOTAL>>>(W3, b1, b2, b3, out);
}

// round 11
// speedup vs baseline: 3.1308x; 3.0412x over previous
#include <cuda_runtime.h>
#include <cuda_bf16.h>
#include <cstdint>

#define MAX_N   (1 << 17)
#define NMODELS 8
#define H       128
#define TILE    128
#define NCTA    148
#define MLP_THREADS 256

// B row stride: 128 bf16 = 256B + 16B pad = 272B = 68 u32 (ldmatrix conflict-free)
#define BSTRIDE_U32 68
#define BUF_U32     (H * BSTRIDE_U32)      // 8704 u32 = 34816 B per image

// ---------------- scratch (device globals; no allocs allowed) ----------------
__device__ int    g_counts[NMODELS];       // atomic rank counters (self-reset in k_scan)
__device__ int    g_cnt[NMODELS];          // final per-model counts
__device__ int    g_tilebase[NMODELS + 1];
__device__ int    g_total_tiles;
__device__ int    g_perm[NMODELS * MAX_N]; // segmented
__device__ float4 g_xg[NMODELS * MAX_N];   // segmented normalized inputs
// transposed bf16 weight images B[n][k] ([layer*8+model][n][k-pairs])
__device__ __align__(16) uint32_t g_Bhi[16 * BUF_U32];
__device__ __align__(16) uint32_t g_Blo[16 * BUF_U32];
// packed layer0: per model, per col: (w0, w1, w2, b0)
__device__ __align__(16) float4   g_W0p[NMODELS * H];

// ---------------- helpers -----------------------------------------------------
__device__ __forceinline__ uint32_t smem_u32(const void* p) {
    uint32_t a;
    asm("{ .reg .u64 t; cvta.to.shared.u64 t, %1; cvt.u32.u64 %0, t; }"
        : "=r"(a) : "l"(p));
    return a;
}
__device__ __forceinline__ void mma16816(float* d, const uint32_t* a,
                                         uint32_t b0, uint32_t b1) {
    asm volatile(
        "mma.sync.aligned.m16n8k16.row.col.f32.bf16.bf16.f32 "
        "{%0,%1,%2,%3}, {%4,%5,%6,%7}, {%8,%9}, {%0,%1,%2,%3};"
        : "+f"(d[0]), "+f"(d[1]), "+f"(d[2]), "+f"(d[3])
        : "r"(a[0]), "r"(a[1]), "r"(a[2]), "r"(a[3]), "r"(b0), "r"(b1));
}
__device__ __forceinline__ void ldsm4(uint32_t* r, uint32_t addr) {
    asm volatile("ldmatrix.sync.aligned.m8n8.x4.shared.b16 {%0,%1,%2,%3}, [%4];"
                 : "=r"(r[0]), "=r"(r[1]), "=r"(r[2]), "=r"(r[3]) : "r"(addr));
}
// pack (v0 -> low half, v1 -> high half) as bf16x2; also return residuals
__device__ __forceinline__ uint32_t pack_hi_res(float v0, float v1,
                                                float& r0, float& r1) {
    __nv_bfloat162 h = {__float2bfloat16_rn(v0), __float2bfloat16_rn(v1)};
    r0 = v0 - __bfloat162float(h.x);
    r1 = v1 - __bfloat162float(h.y);
    uint32_t u;
    memcpy(&u, &h, 4);
    return u;
}
__device__ __forceinline__ uint32_t pack_bf16x2(float lo_val, float hi_val) {
    uint32_t r;   // %1 -> upper half, %2 -> lower half
    asm("cvt.rn.bf16x2.f32 %0, %1, %2;" : "=r"(r) : "f"(hi_val), "f"(lo_val));
    return r;
}

// ---------------- model index (bit-exact vs reference) ------------------------
__device__ __forceinline__ int model_index(float x0, float x1, float x2) {
    const float den = 2.0f + 1e-6f;
    int c0 = (int)((x2 + 1.0f) / den * 2.0f);
    int c1 = (int)((x1 + 1.0f) / den * 2.0f);
    int c2 = (int)((x0 + 1.0f) / den * 2.0f);
    return c0 + 2 * c1 + 4 * c2;
}

// ---------------- pass 1: fused classify+scatter (+weight prep blocks) -------
// blocks [0, SB): bucket points into per-model segments
// blocks [SB, SB+512): bf16 hi/lo weight split for W1/W2
// block  SB+512: pack W0/b0
__global__ void k_scatter_prep(const float* __restrict__ x,
                               const float* __restrict__ mins,
                               const float* __restrict__ maxs, int n, int SB,
                               const float* __restrict__ W0,
                               const float* __restrict__ b0,
                               const float* __restrict__ W1,
                               const float* __restrict__ W2) {
    const int blk = blockIdx.x;
    const int tid = threadIdx.x;
    if (blk < SB) {
        __shared__ int sh_cnt[NMODELS];
        __shared__ int sh_base[NMODELS];
        if (tid < NMODELS) sh_cnt[tid] = 0;
        __syncthreads();
        int i = blk * blockDim.x + tid;
        int m = 0, rank = 0;
        float x0 = 0.f, x1 = 0.f, x2 = 0.f;
        if (i < n) {
            x0 = x[3 * i]; x1 = x[3 * i + 1]; x2 = x[3 * i + 2];
            m = model_index(x0, x1, x2);
            rank = atomicAdd(&sh_cnt[m], 1);
        }
        __syncthreads();
        if (tid < NMODELS)
            sh_base[tid] = sh_cnt[tid] ? atomicAdd(&g_counts[tid], sh_cnt[tid]) : 0;
        __syncthreads();
        if (i < n) {
            int pos = m * MAX_N + sh_base[m] + rank;
            g_perm[pos] = i;
            float mn0 = mins[3 * m], mn1 = mins[3 * m + 1], mn2 = mins[3 * m + 2];
            float mx0 = maxs[3 * m], mx1 = maxs[3 * m + 1], mx2 = maxs[3 * m + 2];
            g_xg[pos] = make_float4(-1.0f + 2.0f * (x0 - mn0) / (mx0 - mn0),
                                    -1.0f + 2.0f * (x1 - mn1) / (mx1 - mn1),
                                    -1.0f + 2.0f * (x2 - mn2) / (mx2 - mn2), 0.0f);
        }
    } else if (blk < SB + 512) {
        int t = (blk - SB) * 256 + tid;        // 0 .. 131071
        int lm = t >> 13;                      // layer*8 + model
        int w  = t & 8191;
        int nn = w >> 6;                       // output row 0..127
        int k2 = w & 63;                       // pair of K columns
        const float* W = ((lm >> 3) ? W2 : W1) + (lm & 7) * H * H;
        int k = 2 * k2;
        float v0 = W[k * H + nn];              // B[n][k] = W[k][n]
        float v1 = W[(k + 1) * H + nn];
        float r0, r1;
        uint32_t hi = pack_hi_res(v0, v1, r0, r1);
        uint32_t lo = pack_bf16x2(r0, r1);
        int off = lm * BUF_U32 + nn * BSTRIDE_U32 + k2;
        g_Bhi[off] = hi;
        g_Blo[off] = lo;
    } else {
        for (int i = tid; i < NMODELS * H; i += 256) {
            int m = i >> 7, c = i & 127;
            g_W0p[i] = make_float4(W0[m * 384 + c], W0[m * 384 + 128 + c],
                                   W0[m * 384 + 256 + c], b0[m * H + c]);
        }
    }
}

// ---------------- pass 2: tiny scan -------------------------------------------
__global__ void k_scan() {
    if (threadIdx.x == 0) {
        int t = 0;
        for (int m = 0; m < NMODELS; m++) {
            int c = g_counts[m];
            g_counts[m] = 0;          // self-reset for graph replay
            g_cnt[m] = c;
            g_tilebase[m] = t;
            t += (c + TILE - 1) / TILE;
        }
        g_tilebase[NMODELS] = t;
        g_total_tiles = t;
    }
}

// ---------------- smem layout (bytes) -----------------------------------------
#define SB_B1HI 0
#define SB_B1LO (SB_B1HI + 34816)
#define SB_B2HI (SB_B1LO + 34816)
#define SB_B2LO (SB_B2HI + 34816)
#define SB_W0P  (SB_B2LO + 34816)          // 128 * float4 = 2048
#define SB_B1   (SB_W0P + 2048)            // 512
#define SB_B2   (SB_B1 + 512)
#define SB_W3   (SB_B2 + 512)
#define SMEM_TOTAL (SB_W3 + 512)

// one GEMM layer: acc[64] += split-bf16( A-frags ) @ B(smem images)
// accumulator-interleaved issue order (d0,d1,d0,d1,...) to break HMMA chains
__device__ __forceinline__ void mma_layer(float* acc,
                                          const uint32_t* a_hi,
                                          const uint32_t* a_lo,
                                          uint32_t bhi_base, uint32_t blo_base,
                                          uint32_t lane_off) {
    #pragma unroll
    for (int kt = 0; kt < 8; kt++) {
        #pragma unroll
        for (int ntp = 0; ntp < 8; ntp++) {
            uint32_t bh[4], bl[4];
            uint32_t off = (uint32_t)(ntp * 16 * 272 + kt * 32) + lane_off;
            ldsm4(bh, bhi_base + off);
            ldsm4(bl, blo_base + off);
            float* d0 = acc + (2 * ntp) * 4;
            float* d1 = acc + (2 * ntp + 1) * 4;
            mma16816(d0, a_hi + kt * 4, bh[0], bh[1]);
            mma16816(d1, a_hi + kt * 4, bh[2], bh[3]);
            mma16816(d0, a_lo + kt * 4, bh[0], bh[1]);
            mma16816(d1, a_lo + kt * 4, bh[2], bh[3]);
            mma16816(d0, a_hi + kt * 4, bl[0], bl[1]);
            mma16816(d1, a_hi + kt * 4, bl[2], bl[3]);
        }
    }
}

// ---------------- persistent fused-MLP kernel ---------------------------------
__global__ void __launch_bounds__(MLP_THREADS, 1)
k_mlp(const float* __restrict__ W3, const float* __restrict__ b1g,
      const float* __restrict__ b2g, const float* __restrict__ b3g,
      float* __restrict__ out) {
    extern __shared__ char smc[];
    const uint32_t sbase = smem_u32(smc);
    const int tid  = threadIdx.x;
    const int wid  = tid >> 5;
    const int lane = tid & 31;
    const int q2   = 2 * (lane & 3);
    const int grp  = lane >> 2;            // 0..7
    const int r0l  = wid * 16 + grp;       // local row A
    const int r1l  = r0l + 8;              // local row B

    // ldmatrix per-lane base offset within a B image
    const uint32_t lane_off =
        (uint32_t)(((lane & 7) + ((lane & 16) ? 8 : 0)) * 272 + ((lane & 8) ? 16 : 0));

    const int T = g_total_tiles;
    const int start = (int)((long long)blockIdx.x * T / NCTA);
    const int end   = (int)((long long)(blockIdx.x + 1) * T / NCTA);

    float4* W0ps = (float4*)(smc + SB_W0P);
    float*  b1s  = (float*)(smc + SB_B1);
    float*  b2s  = (float*)(smc + SB_B2);
    float*  w3s  = (float*)(smc + SB_W3);

    int cur_m = -1;
    float b3v = 0.0f;

    for (int t = start; t < end; t++) {
        int m = 0;
        while (m < NMODELS - 1 && t >= g_tilebase[m + 1]) m++;

        if (m != cur_m) {
            __syncthreads();               // prior tile's ldmatrix readers done
            const uint4* s1h = (const uint4*)(g_Bhi + (0 * 8 + m) * BUF_U32);
            const uint4* s1l = (const uint4*)(g_Blo + (0 * 8 + m) * BUF_U32);
            const uint4* s2h = (const uint4*)(g_Bhi + (1 * 8 + m) * BUF_U32);
            const uint4* s2l = (const uint4*)(g_Blo + (1 * 8 + m) * BUF_U32);
            uint4* d1h = (uint4*)(smc + SB_B1HI);
            uint4* d1l = (uint4*)(smc + SB_B1LO);
            uint4* d2h = (uint4*)(smc + SB_B2HI);
            uint4* d2l = (uint4*)(smc + SB_B2LO);
            for (int i = tid; i < 2176; i += MLP_THREADS) {
                d1h[i] = s1h[i];
                d1l[i] = s1l[i];
                d2h[i] = s2h[i];
                d2l[i] = s2l[i];
            }
            if (tid < H) {
                W0ps[tid] = g_W0p[m * H + tid];
                b1s[tid]  = b1g[m * H + tid];
                b2s[tid]  = b2g[m * H + tid];
                w3s[tid]  = W3[m * H + tid];
            }
            b3v = b3g[m];
            cur_m = m;
            __syncthreads();
        }

        const int row0 = (t - g_tilebase[m]) * TILE;      // within segment
        const int rows = min(TILE, g_cnt[m] - row0);
        const int seg  = m * MAX_N + row0;

        // ---- layer 0: compute A-fragments directly in registers -------------
        float4 xa = (r0l < rows) ? g_xg[seg + r0l] : make_float4(0.f, 0.f, 0.f, 0.f);
        float4 xb = (r1l < rows) ? g_xg[seg + r1l] : make_float4(0.f, 0.f, 0.f, 0.f);

        uint32_t a_hi[32], a_lo[32];
        #pragma unroll
        for (int kt = 0; kt < 8; kt++) {
            int c0 = kt * 16 + q2;
            float4 wA0 = W0ps[c0], wA1 = W0ps[c0 + 1];
            float4 wB0 = W0ps[c0 + 8], wB1 = W0ps[c0 + 9];
            float va0 = fmaxf(fmaf(xa.x, wA0.x, fmaf(xa.y, wA0.y, fmaf(xa.z, wA0.z, wA0.w))), 0.f);
            float va1 = fmaxf(fmaf(xa.x, wA1.x, fmaf(xa.y, wA1.y, fmaf(xa.z, wA1.z, wA1.w))), 0.f);
            float vb0 = fmaxf(fmaf(xb.x, wA0.x, fmaf(xb.y, wA0.y, fmaf(xb.z, wA0.z, wA0.w))), 0.f);
            float vb1 = fmaxf(fmaf(xb.x, wA1.x, fmaf(xb.y, wA1.y, fmaf(xb.z, wA1.z, wA1.w))), 0.f);
            float va2 = fmaxf(fmaf(xa.x, wB0.x, fmaf(xa.y, wB0.y, fmaf(xa.z, wB0.z, wB0.w))), 0.f);
            float va3 = fmaxf(fmaf(xa.x, wB1.x, fmaf(xa.y, wB1.y, fmaf(xa.z, wB1.z, wB1.w))), 0.f);
            float vb2 = fmaxf(fmaf(xb.x, wB0.x, fmaf(xb.y, wB0.y, fmaf(xb.z, wB0.z, wB0.w))), 0.f);
            float vb3 = fmaxf(fmaf(xb.x, wB1.x, fmaf(xb.y, wB1.y, fmaf(xb.z, wB1.z, wB1.w))), 0.f);
            float ra0, ra1, rb0, rb1, ra2, ra3, rb2, rb3;
            a_hi[kt * 4 + 0] = pack_hi_res(va0, va1, ra0, ra1);
            a_hi[kt * 4 + 1] = pack_hi_res(vb0, vb1, rb0, rb1);
            a_hi[kt * 4 + 2] = pack_hi_res(va2, va3, ra2, ra3);
            a_hi[kt * 4 + 3] = pack_hi_res(vb2, vb3, rb2, rb3);
            a_lo[kt * 4 + 0] = pack_bf16x2(ra0, ra1);
            a_lo[kt * 4 + 1] = pack_bf16x2(rb0, rb1);
            a_lo[kt * 4 + 2] = pack_bf16x2(ra2, ra3);
            a_lo[kt * 4 + 3] = pack_bf16x2(rb2, rb3);
        }

        // ---- layer 1 ---------------------------------------------------------
        float acc[64];
        #pragma unroll
        for (int i = 0; i < 64; i++) acc[i] = 0.0f;
        mma_layer(acc, a_hi, a_lo, sbase + SB_B1HI, sbase + SB_B1LO, lane_off);

        // epilogue: bias + relu -> new A-fragments (C frag layout == A frag layout)
        #pragma unroll
        for (int kt = 0; kt < 8; kt++) {
            int ntA = 2 * kt, ntB = 2 * kt + 1;
            int cbA = ntA * 8 + q2, cbB = ntB * 8 + q2;
            float bA0 = b1s[cbA], bA1 = b1s[cbA + 1];
            float bB0 = b1s[cbB], bB1 = b1s[cbB + 1];
            float va0 = fmaxf(acc[ntA * 4 + 0] + bA0, 0.f);
            float va1 = fmaxf(acc[ntA * 4 + 1] + bA1, 0.f);
            float vb0 = fmaxf(acc[ntA * 4 + 2] + bA0, 0.f);
            float vb1 = fmaxf(acc[ntA * 4 + 3] + bA1, 0.f);
            float va2 = fmaxf(acc[ntB * 4 + 0] + bB0, 0.f);
            float va3 = fmaxf(acc[ntB * 4 + 1] + bB1, 0.f);
            float vb2 = fmaxf(acc[ntB * 4 + 2] + bB0, 0.f);
            float vb3 = fmaxf(acc[ntB * 4 + 3] + bB1, 0.f);
            float ra0, ra1, rb0, rb1, ra2, ra3, rb2, rb3;
            a_hi[kt * 4 + 0] = pack_hi_res(va0, va1, ra0, ra1);
            a_hi[kt * 4 + 1] = pack_hi_res(vb0, vb1, rb0, rb1);
            a_hi[kt * 4 + 2] = pack_hi_res(va2, va3, ra2, ra3);
            a_hi[kt * 4 + 3] = pack_hi_res(vb2, vb3, rb2, rb3);
            a_lo[kt * 4 + 0] = pack_bf16x2(ra0, ra1);
            a_lo[kt * 4 + 1] = pack_bf16x2(rb0, rb1);
            a_lo[kt * 4 + 2] = pack_bf16x2(ra2, ra3);
            a_lo[kt * 4 + 3] = pack_bf16x2(rb2, rb3);
        }

        // ---- layer 2 ---------------------------------------------------------
        #pragma unroll
        for (int i = 0; i < 64; i++) acc[i] = 0.0f;
        mma_layer(acc, a_hi, a_lo, sbase + SB_B2HI, sbase + SB_B2LO, lane_off);

        // ---- layer 3: relu + dot(w3) + cross-lane reduce ---------------------
        float s0 = 0.f, s1 = 0.f;
        #pragma unroll
        for (int nt = 0; nt < 16; nt++) {
            int cb = nt * 8 + q2;
            float w3a = w3s[cb], w3b = w3s[cb + 1];
            float b2a = b2s[cb], b2b = b2s[cb + 1];
            s0 = fmaf(fmaxf(acc[nt * 4 + 0] + b2a, 0.f), w3a, s0);
            s0 = fmaf(fmaxf(acc[nt * 4 + 1] + b2b, 0.f), w3b, s0);
            s1 = fmaf(fmaxf(acc[nt * 4 + 2] + b2a, 0.f), w3a, s1);
            s1 = fmaf(fmaxf(acc[nt * 4 + 3] + b2b, 0.f), w3b, s1);
        }
        s0 += __shfl_xor_sync(0xffffffffu, s0, 1);
        s0 += __shfl_xor_sync(0xffffffffu, s0, 2);
        s1 += __shfl_xor_sync(0xffffffffu, s1, 1);
        s1 += __shfl_xor_sync(0xffffffffu, s1, 2);
        if ((lane & 3) == 0) {
            if (r0l < rows) out[g_perm[seg + r0l]] = s0 + b3v;
            if (r1l < rows) out[g_perm[seg + r1l]] = s1 + b3v;
        }
    }
}

// ---------------- launch -------------------------------------------------------
extern "C" void kernel_launch(void* const* d_in, const int* in_sizes, int n_in,
                              void* d_out, int out_size) {
    const float* x    = (const float*)d_in[0];
    const float* W0   = (const float*)d_in[1];
    const float* b0   = (const float*)d_in[2];
    const float* W1   = (const float*)d_in[3];
    const float* b1   = (const float*)d_in[4];
    const float* W2   = (const float*)d_in[5];
    const float* b2   = (const float*)d_in[6];
    const float* W3   = (const float*)d_in[7];
    const float* b3   = (const float*)d_in[8];
    const float* mins = (const float*)d_in[9];
    const float* maxs = (const float*)d_in[10];
    float* out = (float*)d_out;

    const int n = in_sizes[0] / 3;

    cudaFuncSetAttribute(k_mlp, cudaFuncAttributeMaxDynamicSharedMemorySize,
                         SMEM_TOTAL);

    int blocks = (n + 255) / 256;
    k_scatter_prep<<<blocks + 513, 256>>>(x, mins, maxs, n, blocks,
                                          W0, b0, W1, W2);
    k_scan<<<1, 32>>>();
    k_mlp<<<NCTA, MLP_THREADS, SMEM_TOTAL>>>(W3, b1, b2, b3, out);
}